// round 10
// baseline (speedup 1.0000x reference)
#include <cuda_runtime.h>

#define BB 32
#define CC 256
#define TT 4096
#define NH 8
#define DH 64
#define DK 512     // NH*DH
#define JSPLIT 16
#define JB 256     // j per block
#define JBQ 64     // float4 (16B) units per block j-range

typedef unsigned long long u64;

// Scratch (allocation-free per harness rules)
__device__ float g_qW[BB * NH * CC];            // scale-folded q @ Wkv_k
__device__ float g_pm[JSPLIT * BB * NH];        // block-local softmax max
__device__ float g_ps[JSPLIT * BB * NH];        // block-local softmax sum
__device__ float g_pacc[JSPLIT * BB * NH * CC]; // unnormalized attn·x partials
__device__ float g_xa[BB * NH * CC];            // combined xattn
__device__ float g_oh[BB * DK];                 // v-projection intermediate

// ---- packed f32x2 helpers (Blackwell FFMA2) ----
__device__ __forceinline__ u64 pk(float a, float b) {
    u64 v; asm("mov.b64 %0,{%1,%2};" : "=l"(v) : "f"(a), "f"(b)); return v;
}
__device__ __forceinline__ float2 upk(u64 v) {
    float2 f; asm("mov.b64 {%0,%1},%2;" : "=f"(f.x), "=f"(f.y) : "l"(v)); return f;
}
__device__ __forceinline__ void ffma2(u64& d, u64 a, u64 b) {
    asm("fma.rn.f32x2 %0,%1,%2,%0;" : "+l"(d) : "l"(a), "l"(b));
}

// ---------------------------------------------------------------------------
// Kernel A: per (n,b): q = query@Wq.T + bq ; qW[b,n,c] = scale * q·Wkv_k[:,c]
// grid = (8 n, 32 b), 256 threads
// ---------------------------------------------------------------------------
__global__ void k_prep(const float* __restrict__ query,
                       const float* __restrict__ Wq,
                       const float* __restrict__ bq,
                       const float* __restrict__ Wkv) {
    const int n = blockIdx.x, b = blockIdx.y;
    const int tid = threadIdx.x, wid = tid >> 5, lane = tid & 31;
    __shared__ float qin[CC];
    __shared__ float qs[DH];

    qin[tid] = query[b * CC + tid];
    __syncthreads();

    const float4* qv = (const float4*)qin;
    for (int d = wid; d < DH; d += 8) {
        const float4* wr = (const float4*)(Wq + (size_t)(n * DH + d) * CC);
        float s = 0.f;
#pragma unroll
        for (int i = 0; i < 2; ++i) {
            const float4 w = wr[lane + i * 32];
            const float4 q4 = qv[lane + i * 32];
            s += w.x * q4.x + w.y * q4.y + w.z * q4.z + w.w * q4.w;
        }
#pragma unroll
        for (int o = 16; o; o >>= 1) s += __shfl_xor_sync(~0u, s, o);
        if (!lane) qs[d] = s + bq[n * DH + d];
    }
    __syncthreads();

    const float* wbase = Wkv + (size_t)(n * DH) * CC + tid;
    float s = 0.f;
#pragma unroll 8
    for (int d = 0; d < DH; ++d) s += qs[d] * wbase[(size_t)d * CC];
    g_qW[(b * NH + n) * CC + tid] = s * 0.125f;  // 1/sqrt(64)
}

// ---------------------------------------------------------------------------
// Kernel B (fused, single x pass): per (b, j-range of 256):
//   phase1: logits l[8][256] = qW @ x-tile       (x-tile: 256c x 256j, DRAM)
//   phase2: local softmax -> p (unnormalized), m_blk, s_blk
//   phase3: pacc[8][256c] = p @ x-tile^T          (x-tile re-read from L2)
// grid = (16 jr, 32 b), 256 threads.
// ---------------------------------------------------------------------------
__global__ void __launch_bounds__(256, 2) k_fused(const float* __restrict__ x) {
    const int jr = blockIdx.x, b = blockIdx.y;
    const int tid = threadIdx.x, lane = tid & 31, wid = tid >> 5;
    const int cq = tid >> 6;    // c-quarter 0..3 (64 rows each)
    const int jql = tid & 63;   // local 16B-unit j index
    const int jq0 = jr * JBQ;

    __shared__ u64 qw2[CC][NH];            // packed {w,w}, 16 KB
    __shared__ u64 lbuf[4][64][NH][2];     // logit partials, 32 KB
    __shared__ float ps[NH][JB];           // logits -> exp(l-m), 8 KB

    for (int i = tid; i < CC * NH; i += 256) {
        const int c = i >> 3, n = i & 7;
        const float w = g_qW[(b * NH + n) * CC + c];
        qw2[c][n] = pk(w, w);
    }
    __syncthreads();

    // ---- phase 1: logits for this block's 256 j, c-quarter per thread-group
    u64 acc2[NH][2];
#pragma unroll
    for (int n = 0; n < NH; ++n) { acc2[n][0] = 0ull; acc2[n][1] = 0ull; }

    const ulonglong2* xp =
        (const ulonglong2*)(x + ((size_t)b * CC + cq * 64) * TT) + jq0 + jql;
#pragma unroll 4
    for (int i = 0; i < 64; ++i) {
        const ulonglong2 xv = xp[(size_t)i * (TT / 4)];
        const int c = cq * 64 + i;
#pragma unroll
        for (int n = 0; n < NH; ++n) {
            const u64 w = qw2[c][n];
            ffma2(acc2[n][0], w, xv.x);
            ffma2(acc2[n][1], w, xv.y);
        }
    }
#pragma unroll
    for (int n = 0; n < NH; ++n) {
        lbuf[cq][jql][n][0] = acc2[n][0];
        lbuf[cq][jql][n][1] = acc2[n][1];
    }
    __syncthreads();

    // ---- reduce over the 4 c-quarters: 512 (jj,n) pairs, 2 per thread
#pragma unroll
    for (int p = 2 * tid; p < 2 * tid + 2; ++p) {
        const int jj = p >> 3, n = p & 7;
        float2 a0 = upk(lbuf[0][jj][n][0]);
        float2 a1 = upk(lbuf[0][jj][n][1]);
#pragma unroll
        for (int q = 1; q < 4; ++q) {
            const float2 b0 = upk(lbuf[q][jj][n][0]);
            const float2 b1 = upk(lbuf[q][jj][n][1]);
            a0.x += b0.x; a0.y += b0.y; a1.x += b1.x; a1.y += b1.y;
        }
        ps[n][jj * 4 + 0] = a0.x; ps[n][jj * 4 + 1] = a0.y;
        ps[n][jj * 4 + 2] = a1.x; ps[n][jj * 4 + 3] = a1.y;
    }
    __syncthreads();

    // ---- phase 2: local softmax, warp wid owns head wid
    {
        float m = -1e30f;
        for (int j = lane; j < JB; j += 32) m = fmaxf(m, ps[wid][j]);
#pragma unroll
        for (int o = 16; o; o >>= 1) m = fmaxf(m, __shfl_xor_sync(~0u, m, o));
        float s = 0.f;
        for (int j = lane; j < JB; j += 32) {
            const float e = __expf(ps[wid][j] - m);
            ps[wid][j] = e;
            s += e;
        }
#pragma unroll
        for (int o = 16; o; o >>= 1) s += __shfl_xor_sync(~0u, s, o);
        if (!lane) {
            g_pm[(jr * BB + b) * NH + wid] = m;
            g_ps[(jr * BB + b) * NH + wid] = s;
        }
    }
    __syncthreads();

    // ---- phase 3: pacc[n][c] = sum_j p[n][j] * x[c][j]; warp owns 4 c-rows
    const ulonglong2* xq = (const ulonglong2*)(x + (size_t)b * CC * TT) + jq0;
    for (int it = 0; it < 8; ++it) {
        const int c0 = it * 32 + wid * 4;
        u64 a2[NH][4];
#pragma unroll
        for (int n = 0; n < NH; ++n)
#pragma unroll
            for (int cc = 0; cc < 4; ++cc) a2[n][cc] = 0ull;

#pragma unroll
        for (int st = 0; st < 2; ++st) {
            const int jq = lane + st * 32;
            ulonglong2 xv[4];
#pragma unroll
            for (int cc = 0; cc < 4; ++cc)
                xv[cc] = xq[(size_t)(c0 + cc) * (TT / 4) + jq];
#pragma unroll
            for (int n = 0; n < NH; ++n) {
                const ulonglong2 p2 = ((const ulonglong2*)&ps[n][0])[jq];
#pragma unroll
                for (int cc = 0; cc < 4; ++cc) {
                    ffma2(a2[n][cc], p2.x, xv[cc].x);
                    ffma2(a2[n][cc], p2.y, xv[cc].y);
                }
            }
        }
#pragma unroll
        for (int n = 0; n < NH; ++n)
#pragma unroll
            for (int cc = 0; cc < 4; ++cc) {
                const float2 f = upk(a2[n][cc]);
                float v = f.x + f.y;
#pragma unroll
                for (int o = 16; o; o >>= 1) v += __shfl_xor_sync(~0u, v, o);
                if (!lane)
                    g_pacc[((size_t)(jr * BB + b) * NH + n) * CC + c0 + cc] = v;
            }
    }
}

// ---------------------------------------------------------------------------
// Kernel C: combine split-softmax partials.
// grid = (8 n, 32 b), 256 threads (one per c).
// ---------------------------------------------------------------------------
__global__ void k_combine() {
    const int n = blockIdx.x, b = blockIdx.y;
    const int tid = threadIdx.x;
    __shared__ float sm_m[JSPLIT], sm_s[JSPLIT];

    if (tid < JSPLIT) {
        sm_m[tid] = g_pm[(tid * BB + b) * NH + n];
        sm_s[tid] = g_ps[(tid * BB + b) * NH + n];
    }
    __syncthreads();

    float M = -1e30f;
#pragma unroll
    for (int jr = 0; jr < JSPLIT; ++jr) M = fmaxf(M, sm_m[jr]);
    float S = 0.f;
#pragma unroll
    for (int jr = 0; jr < JSPLIT; ++jr) S += sm_s[jr] * __expf(sm_m[jr] - M);

    float acc = 0.f;
#pragma unroll
    for (int jr = 0; jr < JSPLIT; ++jr)
        acc += __expf(sm_m[jr] - M) *
               g_pacc[((size_t)(jr * BB + b) * NH + n) * CC + tid];
    g_xa[(b * NH + n) * CC + tid] = acc / S;
}

// ---------------------------------------------------------------------------
// Kernel D1: oh[b,nd] = Wkv_v[nd]·xa[b,n] + bkv_v[nd]
// grid = (16 nd-tiles of 32, 4 b-groups of 8), 256 threads, thread-per-output.
// ---------------------------------------------------------------------------
__global__ void __launch_bounds__(256) k_out1(const float* __restrict__ Wkv,
                                              const float* __restrict__ bkv) {
    const int ndt = blockIdx.x, bg = blockIdx.y;
    const int n = ndt >> 1;                 // head of this 32-row nd tile
    const int tid = threadIdx.x;
    __shared__ float ws[32][260];           // 32 weight rows, padded
    __shared__ float xs[8][260];            // 8 batches of xattn, padded

    const float4* wsrc = (const float4*)(Wkv + (size_t)(DK + ndt * 32) * CC);
    for (int i = tid; i < 32 * 64; i += 256)
        *(float4*)&ws[i >> 6][(i & 63) * 4] = wsrc[i];
    for (int i = tid; i < 8 * 64; i += 256) {
        const int bl = i >> 6, c4 = i & 63;
        const size_t gi = ((size_t)((bg * 8 + bl) * NH + n)) * CC + c4 * 4;
        *(float4*)&xs[bl][c4 * 4] = *(const float4*)&g_xa[gi];
    }
    __syncthreads();

    const int ndl = tid >> 3, bl = tid & 7;
    float acc = 0.f;
#pragma unroll 8
    for (int c4 = 0; c4 < 64; ++c4) {
        const float4 w = *(const float4*)&ws[ndl][c4 * 4];
        const float4 v = *(const float4*)&xs[bl][c4 * 4];
        acc += w.x * v.x + w.y * v.y + w.z * v.z + w.w * v.w;
    }
    const int nd = ndt * 32 + ndl;
    g_oh[(bg * 8 + bl) * DK + nd] = acc + bkv[DK + nd];
}

// ---------------------------------------------------------------------------
// Kernel D2: y[b,o] = relu(oh[b]·Wfc[o] + bfc[o])
// grid = (8 o-tiles of 32, 4 b-groups of 8), 256 threads, thread-per-output.
// ---------------------------------------------------------------------------
__global__ void __launch_bounds__(256) k_out2(const float* __restrict__ Wfc,
                                              const float* __restrict__ bfc,
                                              float* __restrict__ out) {
    const int ot = blockIdx.x, bg = blockIdx.y;
    const int tid = threadIdx.x;
    __shared__ float ws[32][516];           // 32 weight rows (DK=512), padded
    __shared__ float xs[8][516];            // 8 batches of oh, padded

    const float4* wsrc = (const float4*)(Wfc + (size_t)(ot * 32) * DK);
    for (int i = tid; i < 32 * 128; i += 256)
        *(float4*)&ws[i >> 7][(i & 127) * 4] = wsrc[i];
    for (int i = tid; i < 8 * 128; i += 256) {
        const int bl = i >> 7, k4 = i & 127;
        *(float4*)&xs[bl][k4 * 4] =
            *(const float4*)&g_oh[(bg * 8 + bl) * DK + k4 * 4];
    }
    __syncthreads();

    const int ol = tid >> 3, bl = tid & 7;
    float acc = 0.f;
#pragma unroll 8
    for (int k4 = 0; k4 < 128; ++k4) {
        const float4 w = *(const float4*)&ws[ol][k4 * 4];
        const float4 v = *(const float4*)&xs[bl][k4 * 4];
        acc += w.x * v.x + w.y * v.y + w.z * v.z + w.w * v.w;
    }
    const int o = ot * 32 + ol;
    out[(bg * 8 + bl) * CC + o] = fmaxf(acc + bfc[o], 0.f);
}

// ---------------------------------------------------------------------------
extern "C" void kernel_launch(void* const* d_in, const int* in_sizes, int n_in,
                              void* d_out, int out_size) {
    const float* x     = (const float*)d_in[0];  // (32,256,64,64)
    const float* query = (const float*)d_in[1];  // (32,256)
    const float* Wkv   = (const float*)d_in[2];  // (1024,256)
    const float* bkv   = (const float*)d_in[3];  // (1024)
    const float* Wq    = (const float*)d_in[4];  // (512,256)
    const float* bq    = (const float*)d_in[5];  // (512)
    const float* Wfc   = (const float*)d_in[6];  // (256,512)
    const float* bfc   = (const float*)d_in[7];  // (256)
    float* out = (float*)d_out;                  // (32,256)

    k_prep<<<dim3(NH, BB), 256>>>(query, Wq, bq, Wkv);
    k_fused<<<dim3(JSPLIT, BB), 256>>>(x);
    k_combine<<<dim3(NH, BB), 256>>>();
    k_out1<<<dim3(16, 4), 256>>>(Wkv, bkv);
    k_out2<<<dim3(NH, 4), 256>>>(Wfc, bfc, out);
}